// round 3
// baseline (speedup 1.0000x reference)
#include <cuda_runtime.h>
#include <stdint.h>

#define N_NODES   100000
#define N_EDGES   1600000
#define D         128
#define N_LAYERS  3
#define N_CLASSES 10
#define N_GRAPHS  512
#define BN_EPS    1e-5f

// ---------------------------------------------------------------------------
// Static device scratch
// ---------------------------------------------------------------------------
__device__ float g_bufA[(size_t)N_NODES * D];
__device__ float g_bufB[(size_t)N_NODES * D];
__device__ int   g_deg[N_NODES];
__device__ int   g_off[N_NODES + 1];
__device__ int   g_cur[N_NODES];
__device__ int   g_csr[N_EDGES];
__device__ float g_sum[D];
__device__ float g_sumsq[D];
__device__ float g_scale[D];
__device__ float g_shift[D];
__device__ float g_pool[N_GRAPHS * D];
__device__ float g_cnt[N_GRAPHS];

// ---------------------------------------------------------------------------
// Packed f32x2 helpers (sm_100+: fma.rn.f32x2 — 2x fp32 FMA rate)
// ---------------------------------------------------------------------------
__device__ __forceinline__ unsigned long long ffma2(unsigned long long a,
                                                    unsigned long long b,
                                                    unsigned long long c) {
    unsigned long long d;
    asm("fma.rn.f32x2 %0, %1, %2, %3;" : "=l"(d) : "l"(a), "l"(b), "l"(c));
    return d;
}
__device__ __forceinline__ void unpack2(unsigned long long v, float& lo, float& hi) {
    unsigned int a, b;
    asm("mov.b64 {%0, %1}, %2;" : "=r"(a), "=r"(b) : "l"(v));
    lo = __uint_as_float(a);
    hi = __uint_as_float(b);
}

// ---------------------------------------------------------------------------
// CSR build
// ---------------------------------------------------------------------------
__global__ void zero_deg_kernel() {
    for (int i = blockIdx.x * blockDim.x + threadIdx.x; i < N_NODES;
         i += gridDim.x * blockDim.x)
        g_deg[i] = 0;
}
__global__ void hist_kernel(const int* __restrict__ dstA) {
    for (int e = blockIdx.x * blockDim.x + threadIdx.x; e < N_EDGES;
         e += gridDim.x * blockDim.x)
        atomicAdd(&g_deg[dstA[e]], 1);
}
__global__ void scan_kernel() {
    const int T = 1024;
    const int chunk = (N_NODES + T - 1) / T;
    int tid = threadIdx.x;
    int lo = tid * chunk, hi = lo + chunk;
    if (hi > N_NODES) hi = N_NODES;
    if (lo > N_NODES) lo = N_NODES;
    int s = 0;
    for (int i = lo; i < hi; i++) s += g_deg[i];
    __shared__ int sm[T];
    sm[tid] = s;
    __syncthreads();
    for (int off = 1; off < T; off <<= 1) {
        int v = (tid >= off) ? sm[tid - off] : 0;
        __syncthreads();
        sm[tid] += v;
        __syncthreads();
    }
    int run = (tid == 0) ? 0 : sm[tid - 1];
    for (int i = lo; i < hi; i++) {
        g_off[i] = run;
        g_cur[i] = run;
        run += g_deg[i];
    }
    if (tid == T - 1) g_off[N_NODES] = run;
}
__global__ void fill_kernel(const int* __restrict__ srcA,
                            const int* __restrict__ dstA) {
    for (int e = blockIdx.x * blockDim.x + threadIdx.x; e < N_EDGES;
         e += gridDim.x * blockDim.x) {
        int p = atomicAdd(&g_cur[dstA[e]], 1);
        g_csr[p] = srcA[e];
    }
}

// ---------------------------------------------------------------------------
// BN affine
// ---------------------------------------------------------------------------
__global__ void init_affine_kernel() {
    int t = threadIdx.x;
    if (t < D) { g_scale[t] = 1.0f; g_shift[t] = 0.0f; }
}
__global__ void zero_stats_kernel() {
    int t = threadIdx.x;
    if (t < D) { g_sum[t] = 0.0f; g_sumsq[t] = 0.0f; }
}
__global__ void bn_finalize_kernel(const float* __restrict__ gamma,
                                   const float* __restrict__ beta) {
    int t = threadIdx.x;
    if (t < D) {
        float mu  = g_sum[t]   * (1.0f / (float)N_NODES);
        float var = g_sumsq[t] * (1.0f / (float)N_NODES) - mu * mu;
        if (var < 0.0f) var = 0.0f;
        float inv = rsqrtf(var + BN_EPS);
        float sc  = gamma[t] * inv;
        g_scale[t] = sc;
        g_shift[t] = beta[t] - mu * sc;
    }
}

// ---------------------------------------------------------------------------
// Aggregation: out = scale ⊙ (x_i + Σ_{j->i} x_j) + (1+deg)·shift
// ---------------------------------------------------------------------------
__global__ void __launch_bounds__(256)
aggregate_kernel(const float* __restrict__ xin, float* __restrict__ out) {
    int warp = threadIdx.x >> 5;
    int lane = threadIdx.x & 31;
    int node = blockIdx.x * 8 + warp;
    if (node >= N_NODES) return;
    int c0 = lane * 4;

    float4 acc0 = *reinterpret_cast<const float4*>(&xin[(size_t)node * D + c0]);
    float4 acc1 = make_float4(0.f, 0.f, 0.f, 0.f);
    int s = g_off[node], e = g_off[node + 1];
    int deg = e - s;

    int b = s;
    for (; b + 32 <= e; b += 32) {
        int idx = g_csr[b + lane];
        #pragma unroll
        for (int t = 0; t < 32; t += 2) {
            int j0 = __shfl_sync(0xffffffffu, idx, t);
            int j1 = __shfl_sync(0xffffffffu, idx, t + 1);
            float4 v0 = *reinterpret_cast<const float4*>(&xin[(size_t)j0 * D + c0]);
            float4 v1 = *reinterpret_cast<const float4*>(&xin[(size_t)j1 * D + c0]);
            acc0.x += v0.x; acc0.y += v0.y; acc0.z += v0.z; acc0.w += v0.w;
            acc1.x += v1.x; acc1.y += v1.y; acc1.z += v1.z; acc1.w += v1.w;
        }
    }
    if (b < e) {
        int idx = (b + lane < e) ? g_csr[b + lane] : 0;
        int m = e - b;
        for (int t = 0; t < m; t++) {
            int j = __shfl_sync(0xffffffffu, idx, t);
            float4 v = *reinterpret_cast<const float4*>(&xin[(size_t)j * D + c0]);
            acc0.x += v.x; acc0.y += v.y; acc0.z += v.z; acc0.w += v.w;
        }
    }
    acc0.x += acc1.x; acc0.y += acc1.y; acc0.z += acc1.z; acc0.w += acc1.w;

    float4 sc = *reinterpret_cast<const float4*>(&g_scale[c0]);
    float4 sh = *reinterpret_cast<const float4*>(&g_shift[c0]);
    float dp1 = (float)(deg + 1);
    float4 o;
    o.x = sc.x * acc0.x + dp1 * sh.x;
    o.y = sc.y * acc0.y + dp1 * sh.y;
    o.z = sc.z * acc0.z + dp1 * sh.z;
    o.w = sc.w * acc0.w + dp1 * sh.w;
    *reinterpret_cast<float4*>(&out[(size_t)node * D + c0]) = o;
}

// ---------------------------------------------------------------------------
// GEMM: C = relu(A @ W + b). 128x128 tile per CTA, 256 threads, 8x8/thread.
// A stored in smem DUPLICATED ({a,a} pairs) so FFMA2 operands come straight
// from LDS.64 (no mov.b64 pack). W resident in smem (row-major [k][n]).
// STATS=1 additionally accumulates per-column sum / sum-of-squares.
// ---------------------------------------------------------------------------
#define ASTRIDE 260                     // floats per duplicated A row (2*128+pad)
#define SM_W    0                       // 16384 floats
#define SM_A    16384                   // 128*260 = 33280 floats
#define SM_BIAS (16384 + 33280)         // 128
#define SM_SUM  (SM_BIAS + 128)         // 128
#define SM_SQ   (SM_SUM + 128)          // 128
#define SM_TOT  ((SM_SQ + 128) * 4)     // bytes

template <int STATS>
__global__ void __launch_bounds__(256, 1)
gemm_relu(const float* __restrict__ A, const float* __restrict__ Wm,
          const float* __restrict__ bias, float* __restrict__ Cout) {
    extern __shared__ float smem[];
    float* sW = smem + SM_W;
    float* sA = smem + SM_A;

    const int tid  = threadIdx.x;
    const int row0 = blockIdx.x * 128;

    // W: straight copy (row-major [k][n])
    #pragma unroll
    for (int i = tid * 4; i < D * D; i += 256 * 4)
        *reinterpret_cast<float4*>(&sW[i]) =
            *reinterpret_cast<const float4*>(&Wm[i]);

    // A tile: 128 x 128, stored duplicated: element k at sA[m*ASTRIDE + 2k(+1)]
    for (int i = tid; i < 128 * 32; i += 256) {
        int m  = i >> 5;
        int k4 = (i & 31) << 2;
        float4 v = make_float4(0.f, 0.f, 0.f, 0.f);
        if (row0 + m < N_NODES)
            v = *reinterpret_cast<const float4*>(&A[(size_t)(row0 + m) * D + k4]);
        float* base = &sA[m * ASTRIDE + k4 * 2];
        *reinterpret_cast<float4*>(base)     = make_float4(v.x, v.x, v.y, v.y);
        *reinterpret_cast<float4*>(base + 4) = make_float4(v.z, v.z, v.w, v.w);
    }
    if (tid < D) {
        smem[SM_BIAS + tid] = bias[tid];
        if (STATS) { smem[SM_SUM + tid] = 0.0f; smem[SM_SQ + tid] = 0.0f; }
    }
    __syncthreads();

    const int tx   = tid & 15;            // 16 col groups
    const int ty   = tid >> 4;            // 16 row groups
    const int col0 = tx * 8;
    const int r0   = ty * 8;

    unsigned long long acc[8][4];
    #pragma unroll
    for (int r = 0; r < 8; r++)
        #pragma unroll
        for (int c = 0; c < 4; c++) acc[r][c] = 0ull;

    const float* aBase = &sA[r0 * ASTRIDE];
    #pragma unroll 2
    for (int k = 0; k < D; k++) {
        unsigned long long wv[4];
        const float* wrow = &sW[k * D + col0];
        #pragma unroll
        for (int c = 0; c < 4; c++)
            wv[c] = *reinterpret_cast<const unsigned long long*>(wrow + 2 * c);
        #pragma unroll
        for (int r = 0; r < 8; r++) {
            unsigned long long av =
                *reinterpret_cast<const unsigned long long*>(
                    aBase + r * ASTRIDE + 2 * k);
            #pragma unroll
            for (int c = 0; c < 4; c++)
                acc[r][c] = ffma2(av, wv[c], acc[r][c]);
        }
    }

    float bv[8];
    #pragma unroll
    for (int c = 0; c < 8; c++) bv[c] = smem[SM_BIAS + col0 + c];

    float lsum[8], lsq[8];
    if (STATS) {
        #pragma unroll
        for (int c = 0; c < 8; c++) { lsum[c] = 0.0f; lsq[c] = 0.0f; }
    }

    #pragma unroll
    for (int r = 0; r < 8; r++) {
        int gr = row0 + r0 + r;
        if (gr >= N_NODES) break;
        float v[8];
        #pragma unroll
        for (int c = 0; c < 4; c++) {
            float lo, hi;
            unpack2(acc[r][c], lo, hi);
            v[2 * c]     = fmaxf(lo + bv[2 * c], 0.0f);
            v[2 * c + 1] = fmaxf(hi + bv[2 * c + 1], 0.0f);
        }
        #pragma unroll
        for (int c = 0; c < 2; c++) {
            float4 st = make_float4(v[4 * c], v[4 * c + 1],
                                    v[4 * c + 2], v[4 * c + 3]);
            *reinterpret_cast<float4*>(&Cout[(size_t)gr * D + col0 + 4 * c]) = st;
        }
        if (STATS) {
            #pragma unroll
            for (int c = 0; c < 8; c++) {
                lsum[c] += v[c];
                lsq[c]  += v[c] * v[c];
            }
        }
    }

    if (STATS) {
        #pragma unroll
        for (int c = 0; c < 8; c++) {
            atomicAdd(&smem[SM_SUM + col0 + c], lsum[c]);
            atomicAdd(&smem[SM_SQ + col0 + c], lsq[c]);
        }
        __syncthreads();
        if (tid < D) {
            atomicAdd(&g_sum[tid], smem[SM_SUM + tid]);
            atomicAdd(&g_sumsq[tid], smem[SM_SQ + tid]);
        }
    }
}

// ---------------------------------------------------------------------------
// Pooling + MLP head
// ---------------------------------------------------------------------------
__global__ void zero_pool_kernel() {
    int i = blockIdx.x * blockDim.x + threadIdx.x;
    int n = N_GRAPHS * D + N_GRAPHS;
    for (; i < n; i += gridDim.x * blockDim.x) {
        if (i < N_GRAPHS * D) g_pool[i] = 0.0f;
        else g_cnt[i - N_GRAPHS * D] = 0.0f;
    }
}
__global__ void __launch_bounds__(256)
pool_kernel(const float* __restrict__ xin, const int* __restrict__ batch) {
    int warp = threadIdx.x >> 5;
    int lane = threadIdx.x & 31;
    int node = blockIdx.x * 8 + warp;
    if (node >= N_NODES) return;
    int g  = batch[node];
    int c0 = lane * 4;
    float4 v = *reinterpret_cast<const float4*>(&xin[(size_t)node * D + c0]);
    atomicAdd(&g_pool[g * D + c0 + 0], v.x);
    atomicAdd(&g_pool[g * D + c0 + 1], v.y);
    atomicAdd(&g_pool[g * D + c0 + 2], v.z);
    atomicAdd(&g_pool[g * D + c0 + 3], v.w);
    if (lane == 0) atomicAdd(&g_cnt[g], 1.0f);
}
__global__ void head_kernel(const float* __restrict__ lin1w,
                            const float* __restrict__ lin1b,
                            const float* __restrict__ lin2w,
                            const float* __restrict__ lin2b,
                            float* __restrict__ out) {
    __shared__ float row[D];
    __shared__ float hid[D];
    int g = blockIdx.x;
    int t = threadIdx.x;
    float cnt = g_cnt[g];
    float p = 0.0f;
    if (cnt > 0.0f)
        p = g_scale[t] * g_pool[g * D + t] / cnt + g_shift[t];
    row[t] = p;
    __syncthreads();
    float a = lin1b[t];
    #pragma unroll 8
    for (int k = 0; k < D; k++) a += row[k] * lin1w[k * D + t];
    a = fmaxf(a, 0.0f);
    hid[t] = a;
    __syncthreads();
    if (t < N_CLASSES) {
        float o = lin2b[t];
        #pragma unroll 8
        for (int k = 0; k < D; k++) o += hid[k] * lin2w[k * N_CLASSES + t];
        out[g * N_CLASSES + t] = o;
    }
}

// ---------------------------------------------------------------------------
// Launcher
// ---------------------------------------------------------------------------
extern "C" void kernel_launch(void* const* d_in, const int* in_sizes, int n_in,
                              void* d_out, int out_size) {
    const float* x      = (const float*)d_in[0];
    const int*   ei     = (const int*)  d_in[1];
    const int*   batch  = (const int*)  d_in[2];
    const float* W1s    = (const float*)d_in[3];
    const float* b1s    = (const float*)d_in[4];
    const float* W2s    = (const float*)d_in[5];
    const float* b2s    = (const float*)d_in[6];
    const float* gammas = (const float*)d_in[7];
    const float* betas  = (const float*)d_in[8];
    const float* lin1w  = (const float*)d_in[9];
    const float* lin1b  = (const float*)d_in[10];
    const float* lin2w  = (const float*)d_in[11];
    const float* lin2b  = (const float*)d_in[12];
    float* out = (float*)d_out;

    const int* srcA = ei;
    const int* dstA = ei + N_EDGES;

    cudaFuncSetAttribute(gemm_relu<0>,
                         cudaFuncAttributeMaxDynamicSharedMemorySize, SM_TOT);
    cudaFuncSetAttribute(gemm_relu<1>,
                         cudaFuncAttributeMaxDynamicSharedMemorySize, SM_TOT);

    void *pA, *pB;
    cudaGetSymbolAddress(&pA, g_bufA);
    cudaGetSymbolAddress(&pB, g_bufB);
    float* A = (float*)pA;
    float* B = (float*)pB;

    zero_deg_kernel<<<256, 256>>>();
    hist_kernel<<<2048, 256>>>(dstA);
    scan_kernel<<<1, 1024>>>();
    fill_kernel<<<2048, 256>>>(srcA, dstA);
    init_affine_kernel<<<1, 128>>>();

    const int AGG_BLOCKS  = (N_NODES + 7) / 8;           // 12500
    const int GEMM_BLOCKS = (N_NODES + 127) / 128;       // 782

    const float* cur = x;
    for (int l = 0; l < N_LAYERS; l++) {
        aggregate_kernel<<<AGG_BLOCKS, 256>>>(cur, B);
        gemm_relu<0><<<GEMM_BLOCKS, 256, SM_TOT>>>(B, W1s + l * D * D,
                                                   b1s + l * D, A);
        zero_stats_kernel<<<1, 128>>>();
        gemm_relu<1><<<GEMM_BLOCKS, 256, SM_TOT>>>(A, W2s + l * D * D,
                                                   b2s + l * D, B);
        bn_finalize_kernel<<<1, 128>>>(gammas + l * D, betas + l * D);
        cur = B;
        float* tmp = A; A = B; B = tmp;
    }

    zero_pool_kernel<<<128, 256>>>();
    pool_kernel<<<AGG_BLOCKS, 256>>>(cur, batch);
    head_kernel<<<N_GRAPHS, 128>>>(lin1w, lin1b, lin2w, lin2b, out);
}

// round 5
// speedup vs baseline: 1.0888x; 1.0888x over previous
#include <cuda_runtime.h>
#include <stdint.h>

#define N_NODES   100000
#define N_EDGES   1600000
#define D         128
#define N_LAYERS  3
#define N_CLASSES 10
#define N_GRAPHS  512
#define BN_EPS    1e-5f

// ---------------------------------------------------------------------------
// Static device scratch
// ---------------------------------------------------------------------------
__device__ float g_bufA[(size_t)N_NODES * D];
__device__ float g_bufB[(size_t)N_NODES * D];
__device__ int   g_deg[N_NODES];
__device__ int   g_off[N_NODES + 1];
__device__ int   g_cur[N_NODES];
__device__ int   g_csr[N_EDGES];
__device__ float g_sum[D];
__device__ float g_sumsq[D];
__device__ float g_scale[D];
__device__ float g_shift[D];
__device__ float g_pool[N_GRAPHS * D];
__device__ float g_cnt[N_GRAPHS];

// ---------------------------------------------------------------------------
// Packed f32x2 helpers
// ---------------------------------------------------------------------------
__device__ __forceinline__ unsigned long long ffma2(unsigned long long a,
                                                    unsigned long long b,
                                                    unsigned long long c) {
    unsigned long long d;
    asm("fma.rn.f32x2 %0, %1, %2, %3;" : "=l"(d) : "l"(a), "l"(b), "l"(c));
    return d;
}
__device__ __forceinline__ void unpack2(unsigned long long v, float& lo, float& hi) {
    unsigned int a, b;
    asm("mov.b64 {%0, %1}, %2;" : "=r"(a), "=r"(b) : "l"(v));
    lo = __uint_as_float(a);
    hi = __uint_as_float(b);
}
__device__ __forceinline__ unsigned long long dup2(float x) {
    unsigned long long u = (unsigned long long)__float_as_uint(x);
    return u | (u << 32);
}

// ---------------------------------------------------------------------------
// CSR build
// ---------------------------------------------------------------------------
__global__ void zero_deg_kernel() {
    for (int i = blockIdx.x * blockDim.x + threadIdx.x; i < N_NODES;
         i += gridDim.x * blockDim.x)
        g_deg[i] = 0;
}
__global__ void hist_kernel(const int* __restrict__ dstA) {
    for (int e = blockIdx.x * blockDim.x + threadIdx.x; e < N_EDGES;
         e += gridDim.x * blockDim.x)
        atomicAdd(&g_deg[dstA[e]], 1);
}
__global__ void scan_kernel() {
    const int T = 1024;
    const int chunk = (N_NODES + T - 1) / T;
    int tid = threadIdx.x;
    int lo = tid * chunk, hi = lo + chunk;
    if (hi > N_NODES) hi = N_NODES;
    if (lo > N_NODES) lo = N_NODES;
    int s = 0;
    for (int i = lo; i < hi; i++) s += g_deg[i];
    __shared__ int sm[T];
    sm[tid] = s;
    __syncthreads();
    for (int off = 1; off < T; off <<= 1) {
        int v = (tid >= off) ? sm[tid - off] : 0;
        __syncthreads();
        sm[tid] += v;
        __syncthreads();
    }
    int run = (tid == 0) ? 0 : sm[tid - 1];
    for (int i = lo; i < hi; i++) {
        g_off[i] = run;
        g_cur[i] = run;
        run += g_deg[i];
    }
    if (tid == T - 1) g_off[N_NODES] = run;
}
__global__ void fill_kernel(const int* __restrict__ srcA,
                            const int* __restrict__ dstA) {
    for (int e = blockIdx.x * blockDim.x + threadIdx.x; e < N_EDGES;
         e += gridDim.x * blockDim.x) {
        int p = atomicAdd(&g_cur[dstA[e]], 1);
        g_csr[p] = srcA[e];
    }
}

// ---------------------------------------------------------------------------
// BN affine
// ---------------------------------------------------------------------------
__global__ void init_affine_kernel() {
    int t = threadIdx.x;
    if (t < D) { g_scale[t] = 1.0f; g_shift[t] = 0.0f; }
}
__global__ void zero_stats_kernel() {
    int t = threadIdx.x;
    if (t < D) { g_sum[t] = 0.0f; g_sumsq[t] = 0.0f; }
}
__global__ void bn_finalize_kernel(const float* __restrict__ gamma,
                                   const float* __restrict__ beta) {
    int t = threadIdx.x;
    if (t < D) {
        float mu  = g_sum[t]   * (1.0f / (float)N_NODES);
        float var = g_sumsq[t] * (1.0f / (float)N_NODES) - mu * mu;
        if (var < 0.0f) var = 0.0f;
        float inv = rsqrtf(var + BN_EPS);
        float sc  = gamma[t] * inv;
        g_scale[t] = sc;
        g_shift[t] = beta[t] - mu * sc;
    }
}

// ---------------------------------------------------------------------------
// Aggregation: out = scale ⊙ (x_i + Σ_{j->i} x_j) + (1+deg)·shift
// MLP=4 in the neighbor loop; streaming (.cs) output store.
// NOTE: xin and out must be DIFFERENT buffers.
// ---------------------------------------------------------------------------
__global__ void __launch_bounds__(256)
aggregate_kernel(const float* __restrict__ xin, float* __restrict__ out) {
    int warp = threadIdx.x >> 5;
    int lane = threadIdx.x & 31;
    int node = blockIdx.x * 8 + warp;
    if (node >= N_NODES) return;
    int c0 = lane * 4;

    float4 a0 = *reinterpret_cast<const float4*>(&xin[(size_t)node * D + c0]);
    float4 a1 = make_float4(0.f, 0.f, 0.f, 0.f);
    float4 a2 = make_float4(0.f, 0.f, 0.f, 0.f);
    float4 a3 = make_float4(0.f, 0.f, 0.f, 0.f);
    int s = g_off[node], e = g_off[node + 1];
    int deg = e - s;

    for (int b = s; b < e; b += 32) {
        int m = e - b;
        if (m > 32) m = 32;
        int idx = (lane < m) ? g_csr[b + lane] : 0;
        int t = 0;
        for (; t + 4 <= m; t += 4) {
            int j0 = __shfl_sync(0xffffffffu, idx, t);
            int j1 = __shfl_sync(0xffffffffu, idx, t + 1);
            int j2 = __shfl_sync(0xffffffffu, idx, t + 2);
            int j3 = __shfl_sync(0xffffffffu, idx, t + 3);
            float4 v0 = *reinterpret_cast<const float4*>(&xin[(size_t)j0 * D + c0]);
            float4 v1 = *reinterpret_cast<const float4*>(&xin[(size_t)j1 * D + c0]);
            float4 v2 = *reinterpret_cast<const float4*>(&xin[(size_t)j2 * D + c0]);
            float4 v3 = *reinterpret_cast<const float4*>(&xin[(size_t)j3 * D + c0]);
            a0.x += v0.x; a0.y += v0.y; a0.z += v0.z; a0.w += v0.w;
            a1.x += v1.x; a1.y += v1.y; a1.z += v1.z; a1.w += v1.w;
            a2.x += v2.x; a2.y += v2.y; a2.z += v2.z; a2.w += v2.w;
            a3.x += v3.x; a3.y += v3.y; a3.z += v3.z; a3.w += v3.w;
        }
        for (; t < m; t++) {
            int j = __shfl_sync(0xffffffffu, idx, t);
            float4 v = *reinterpret_cast<const float4*>(&xin[(size_t)j * D + c0]);
            a0.x += v.x; a0.y += v.y; a0.z += v.z; a0.w += v.w;
        }
    }
    a0.x += a1.x + a2.x + a3.x;
    a0.y += a1.y + a2.y + a3.y;
    a0.z += a1.z + a2.z + a3.z;
    a0.w += a1.w + a2.w + a3.w;

    float4 sc = *reinterpret_cast<const float4*>(&g_scale[c0]);
    float4 sh = *reinterpret_cast<const float4*>(&g_shift[c0]);
    float dp1 = (float)(deg + 1);
    float4 o;
    o.x = sc.x * a0.x + dp1 * sh.x;
    o.y = sc.y * a0.y + dp1 * sh.y;
    o.z = sc.z * a0.z + dp1 * sh.z;
    o.w = sc.w * a0.w + dp1 * sh.w;
    __stcs(reinterpret_cast<float4*>(&out[(size_t)node * D + c0]), o);
}

// ---------------------------------------------------------------------------
// Fused layer MLP: C = relu(relu(A@W1+b1)@W2+b2), plus BN stats on C.
// 128x128 tile per CTA, 256 threads, 8x8 per thread, FFMA2 via duplicated A.
// Intermediate h1 tile never leaves shared memory.
// SAFE IN-PLACE (Cout may equal A): each CTA reads only its own 128 rows in
// the prologue and writes only those rows in the epilogue.
// ---------------------------------------------------------------------------
#define ASTRIDE 260
#define SM_W    0
#define SM_A    16384
#define SM_B1   (16384 + 33280)
#define SM_B2   (SM_B1 + 128)
#define SM_SUM  (SM_B2 + 128)
#define SM_SQ   (SM_SUM + 128)
#define SM_TOT  ((SM_SQ + 128) * 4)

__global__ void __launch_bounds__(256, 1)
fused_mlp(const float* __restrict__ A,
          const float* __restrict__ W1, const float* __restrict__ b1,
          const float* __restrict__ W2, const float* __restrict__ b2,
          float* __restrict__ Cout) {
    extern __shared__ float smem[];
    float* sW = smem + SM_W;
    float* sA = smem + SM_A;

    const int tid  = threadIdx.x;
    const int row0 = blockIdx.x * 128;

    // W1 into smem
    #pragma unroll
    for (int i = tid * 4; i < D * D; i += 256 * 4)
        *reinterpret_cast<float4*>(&sW[i]) =
            *reinterpret_cast<const float4*>(&W1[i]);

    // A tile, streaming read, stored duplicated
    for (int i = tid; i < 128 * 32; i += 256) {
        int m  = i >> 5;
        int k4 = (i & 31) << 2;
        float4 v = make_float4(0.f, 0.f, 0.f, 0.f);
        if (row0 + m < N_NODES)
            v = __ldcs(reinterpret_cast<const float4*>(
                    &A[(size_t)(row0 + m) * D + k4]));
        float* base = &sA[m * ASTRIDE + k4 * 2];
        *reinterpret_cast<float4*>(base)     = make_float4(v.x, v.x, v.y, v.y);
        *reinterpret_cast<float4*>(base + 4) = make_float4(v.z, v.z, v.w, v.w);
    }
    if (tid < D) {
        smem[SM_B1 + tid]  = b1[tid];
        smem[SM_B2 + tid]  = b2[tid];
        smem[SM_SUM + tid] = 0.0f;
        smem[SM_SQ + tid]  = 0.0f;
    }
    __syncthreads();

    const int tx   = tid & 15;
    const int ty   = tid >> 4;
    const int col0 = tx * 8;
    const int r0   = ty * 8;
    const float* aBase = &sA[r0 * ASTRIDE];

    // ---- GEMM1 ----
    unsigned long long acc[8][4];
    #pragma unroll
    for (int r = 0; r < 8; r++)
        #pragma unroll
        for (int c = 0; c < 4; c++) acc[r][c] = 0ull;

    #pragma unroll 2
    for (int k = 0; k < D; k++) {
        unsigned long long wv[4];
        const float* wrow = &sW[k * D + col0];
        #pragma unroll
        for (int c = 0; c < 4; c++)
            wv[c] = *reinterpret_cast<const unsigned long long*>(wrow + 2 * c);
        #pragma unroll
        for (int r = 0; r < 8; r++) {
            unsigned long long av =
                *reinterpret_cast<const unsigned long long*>(
                    aBase + r * ASTRIDE + 2 * k);
            #pragma unroll
            for (int c = 0; c < 4; c++)
                acc[r][c] = ffma2(av, wv[c], acc[r][c]);
        }
    }
    __syncthreads();   // all reads of sA / sW complete

    // h1 = relu(acc + b1) -> back into sA (duplicated); W2 -> sW
    {
        float bv[8];
        #pragma unroll
        for (int c = 0; c < 8; c++) bv[c] = smem[SM_B1 + col0 + c];
        #pragma unroll
        for (int r = 0; r < 8; r++) {
            float* dst = &sA[(r0 + r) * ASTRIDE + 2 * col0];
            #pragma unroll
            for (int c = 0; c < 4; c++) {
                float lo, hi;
                unpack2(acc[r][c], lo, hi);
                lo = fmaxf(lo + bv[2 * c], 0.0f);
                hi = fmaxf(hi + bv[2 * c + 1], 0.0f);
                *reinterpret_cast<unsigned long long*>(dst + 4 * c)     = dup2(lo);
                *reinterpret_cast<unsigned long long*>(dst + 4 * c + 2) = dup2(hi);
            }
        }
    }
    #pragma unroll
    for (int i = tid * 4; i < D * D; i += 256 * 4)
        *reinterpret_cast<float4*>(&sW[i]) =
            *reinterpret_cast<const float4*>(&W2[i]);
    __syncthreads();

    // ---- GEMM2 ----
    #pragma unroll
    for (int r = 0; r < 8; r++)
        #pragma unroll
        for (int c = 0; c < 4; c++) acc[r][c] = 0ull;

    #pragma unroll 2
    for (int k = 0; k < D; k++) {
        unsigned long long wv[4];
        const float* wrow = &sW[k * D + col0];
        #pragma unroll
        for (int c = 0; c < 4; c++)
            wv[c] = *reinterpret_cast<const unsigned long long*>(wrow + 2 * c);
        #pragma unroll
        for (int r = 0; r < 8; r++) {
            unsigned long long av =
                *reinterpret_cast<const unsigned long long*>(
                    aBase + r * ASTRIDE + 2 * k);
            #pragma unroll
            for (int c = 0; c < 4; c++)
                acc[r][c] = ffma2(av, wv[c], acc[r][c]);
        }
    }

    // epilogue: relu + b2, store (default policy — next layer gathers this),
    // accumulate BN stats
    float bv[8];
    #pragma unroll
    for (int c = 0; c < 8; c++) bv[c] = smem[SM_B2 + col0 + c];
    float lsum[8], lsq[8];
    #pragma unroll
    for (int c = 0; c < 8; c++) { lsum[c] = 0.0f; lsq[c] = 0.0f; }

    #pragma unroll
    for (int r = 0; r < 8; r++) {
        int gr = row0 + r0 + r;
        if (gr >= N_NODES) break;
        float v[8];
        #pragma unroll
        for (int c = 0; c < 4; c++) {
            float lo, hi;
            unpack2(acc[r][c], lo, hi);
            v[2 * c]     = fmaxf(lo + bv[2 * c], 0.0f);
            v[2 * c + 1] = fmaxf(hi + bv[2 * c + 1], 0.0f);
        }
        #pragma unroll
        for (int c = 0; c < 2; c++) {
            float4 st = make_float4(v[4 * c], v[4 * c + 1],
                                    v[4 * c + 2], v[4 * c + 3]);
            *reinterpret_cast<float4*>(&Cout[(size_t)gr * D + col0 + 4 * c]) = st;
        }
        #pragma unroll
        for (int c = 0; c < 8; c++) {
            lsum[c] += v[c];
            lsq[c]  += v[c] * v[c];
        }
    }

    #pragma unroll
    for (int c = 0; c < 8; c++) {
        atomicAdd(&smem[SM_SUM + col0 + c], lsum[c]);
        atomicAdd(&smem[SM_SQ + col0 + c], lsq[c]);
    }
    __syncthreads();
    if (tid < D) {
        atomicAdd(&g_sum[tid], smem[SM_SUM + tid]);
        atomicAdd(&g_sumsq[tid], smem[SM_SQ + tid]);
    }
}

// ---------------------------------------------------------------------------
// Pooling + MLP head
// ---------------------------------------------------------------------------
__global__ void zero_pool_kernel() {
    int i = blockIdx.x * blockDim.x + threadIdx.x;
    int n = N_GRAPHS * D + N_GRAPHS;
    for (; i < n; i += gridDim.x * blockDim.x) {
        if (i < N_GRAPHS * D) g_pool[i] = 0.0f;
        else g_cnt[i - N_GRAPHS * D] = 0.0f;
    }
}
__global__ void __launch_bounds__(256)
pool_kernel(const float* __restrict__ xin, const int* __restrict__ batch) {
    int warp = threadIdx.x >> 5;
    int lane = threadIdx.x & 31;
    int node = blockIdx.x * 8 + warp;
    if (node >= N_NODES) return;
    int g  = batch[node];
    int c0 = lane * 4;
    float4 v = *reinterpret_cast<const float4*>(&xin[(size_t)node * D + c0]);
    atomicAdd(&g_pool[g * D + c0 + 0], v.x);
    atomicAdd(&g_pool[g * D + c0 + 1], v.y);
    atomicAdd(&g_pool[g * D + c0 + 2], v.z);
    atomicAdd(&g_pool[g * D + c0 + 3], v.w);
    if (lane == 0) atomicAdd(&g_cnt[g], 1.0f);
}
__global__ void head_kernel(const float* __restrict__ lin1w,
                            const float* __restrict__ lin1b,
                            const float* __restrict__ lin2w,
                            const float* __restrict__ lin2b,
                            float* __restrict__ out) {
    __shared__ float row[D];
    __shared__ float hid[D];
    int g = blockIdx.x;
    int t = threadIdx.x;
    float cnt = g_cnt[g];
    float p = 0.0f;
    if (cnt > 0.0f)
        p = g_scale[t] * g_pool[g * D + t] / cnt + g_shift[t];
    row[t] = p;
    __syncthreads();
    float a = lin1b[t];
    #pragma unroll 8
    for (int k = 0; k < D; k++) a += row[k] * lin1w[k * D + t];
    a = fmaxf(a, 0.0f);
    hid[t] = a;
    __syncthreads();
    if (t < N_CLASSES) {
        float o = lin2b[t];
        #pragma unroll 8
        for (int k = 0; k < D; k++) o += hid[k] * lin2w[k * N_CLASSES + t];
        out[g * N_CLASSES + t] = o;
    }
}

// ---------------------------------------------------------------------------
// Launcher
// ---------------------------------------------------------------------------
extern "C" void kernel_launch(void* const* d_in, const int* in_sizes, int n_in,
                              void* d_out, int out_size) {
    const float* x      = (const float*)d_in[0];
    const int*   ei     = (const int*)  d_in[1];
    const int*   batch  = (const int*)  d_in[2];
    const float* W1s    = (const float*)d_in[3];
    const float* b1s    = (const float*)d_in[4];
    const float* W2s    = (const float*)d_in[5];
    const float* b2s    = (const float*)d_in[6];
    const float* gammas = (const float*)d_in[7];
    const float* betas  = (const float*)d_in[8];
    const float* lin1w  = (const float*)d_in[9];
    const float* lin1b  = (const float*)d_in[10];
    const float* lin2w  = (const float*)d_in[11];
    const float* lin2b  = (const float*)d_in[12];
    float* out = (float*)d_out;

    const int* srcA = ei;
    const int* dstA = ei + N_EDGES;

    cudaFuncSetAttribute(fused_mlp,
                         cudaFuncAttributeMaxDynamicSharedMemorySize, SM_TOT);

    void *pA, *pB;
    cudaGetSymbolAddress(&pA, g_bufA);
    cudaGetSymbolAddress(&pB, g_bufB);
    float* bufs[2] = { (float*)pA, (float*)pB };

    zero_deg_kernel<<<256, 256>>>();
    hist_kernel<<<2048, 256>>>(dstA);
    scan_kernel<<<1, 1024>>>();
    fill_kernel<<<2048, 256>>>(srcA, dstA);
    init_affine_kernel<<<1, 128>>>();

    const int AGG_BLOCKS  = (N_NODES + 7) / 8;           // 12500
    const int GEMM_BLOCKS = (N_NODES + 127) / 128;       // 782

    const float* cur = x;
    for (int l = 0; l < N_LAYERS; l++) {
        float* t = bufs[l & 1];        // always != cur
        aggregate_kernel<<<AGG_BLOCKS, 256>>>(cur, t);
        zero_stats_kernel<<<1, 128>>>();
        fused_mlp<<<GEMM_BLOCKS, 256, SM_TOT>>>(t, W1s + l * D * D,
                                                b1s + l * D,
                                                W2s + l * D * D,
                                                b2s + l * D, t);  // in-place
        bn_finalize_kernel<<<1, 128>>>(gammas + l * D, betas + l * D);
        cur = t;
    }

    zero_pool_kernel<<<128, 256>>>();
    pool_kernel<<<AGG_BLOCKS, 256>>>(cur, batch);
    head_kernel<<<N_GRAPHS, 128>>>(lin1w, lin1b, lin2w, lin2b, out);
}